// round 12
// baseline (speedup 1.0000x reference)
#include <cuda_runtime.h>
#include <cuda_fp16.h>
#include <math.h>
#include <stdint.h>

#define BS   1024
#define SEQ  360
#define DIM  512
#define MTOT (BS*SEQ)

// ===================== scratch =====================
__device__ float g_hproj[BS * DIM];          // relu(hidden @ W2^T + b2)
__device__ float g_score[BS * SEQ];          // pre-softmax scores
__device__ __half g_w1f[DIM * DIM];          // W1 fp16
__device__ int   g_cnt[BS];                  // per-batch CTA completion counters

// ===================== helpers =====================
__device__ __forceinline__ uint32_t smem_u32(const void* p) {
    uint32_t a;
    asm("{ .reg .u64 t; cvta.to.shared.u64 t, %1; cvt.u32.u64 %0, t; }" : "=r"(a) : "l"(p));
    return a;
}
__device__ __forceinline__ void ldsm4(uint32_t* r, uint32_t addr) {
    asm volatile("ldmatrix.sync.aligned.m8n8.x4.shared.b16 {%0,%1,%2,%3}, [%4];"
                 : "=r"(r[0]), "=r"(r[1]), "=r"(r[2]), "=r"(r[3]) : "r"(addr));
}
__device__ __forceinline__ void mma16816_f16(float* c, uint32_t a0, uint32_t a1,
                                             uint32_t a2, uint32_t a3,
                                             uint32_t b0, uint32_t b1) {
    asm volatile("mma.sync.aligned.m16n8k16.row.col.f32.f16.f16.f32 "
                 "{%0,%1,%2,%3}, {%4,%5,%6,%7}, {%8,%9}, {%0,%1,%2,%3};"
                 : "+f"(c[0]), "+f"(c[1]), "+f"(c[2]), "+f"(c[3])
                 : "r"(a0), "r"(a1), "r"(a2), "r"(a3), "r"(b0), "r"(b1));
}
#define CPA16(smaddr, gptr) \
    asm volatile("cp.async.cg.shared.global [%0], [%1], 16;" :: "r"(smaddr), "l"(gptr))
#define CPA_COMMIT() asm volatile("cp.async.commit_group;" ::: "memory")
#define CPA_WAIT1()  asm volatile("cp.async.wait_group 1;" ::: "memory")

__device__ __forceinline__ uint32_t cvt_f16x2(float hi, float lo) {
    uint32_t d; asm("cvt.rn.f16x2.f32 %0, %1, %2;" : "=r"(d) : "f"(hi), "f"(lo)); return d;
}
__device__ __forceinline__ uint32_t hmax2_0(uint32_t x) {
    uint32_t d; asm("max.f16x2 %0, %1, %2;" : "=r"(d) : "r"(x), "r"(0u)); return d;
}
__device__ __forceinline__ uint32_t hadd2(uint32_t a, uint32_t b) {
    uint32_t d; asm("add.f16x2 %0, %1, %2;" : "=r"(d) : "r"(a), "r"(b)); return d;
}
__device__ __forceinline__ uint32_t htanh2(uint32_t x) {
    uint32_t d; asm("tanh.approx.f16x2 %0, %1;" : "=r"(d) : "r"(x)); return d;
}
__device__ __forceinline__ uint32_t pkh2(float lo, float hi) {
    __half2 h = __floats2half2_rn(lo, hi);   // .x = lo
    return *(uint32_t*)&h;
}
__device__ __forceinline__ uint32_t cvt4_f16(float4 x, uint32_t& hi2) {
    hi2 = pkh2(x.z, x.w);
    return pkh2(x.x, x.y);
}

// ===================== prep: W1 -> fp16 + zero batch counters =====================
__global__ void __launch_bounds__(256) prep_w1_kernel(const float* __restrict__ W1) {
    if (blockIdx.x < 4) g_cnt[blockIdx.x * 256 + threadIdx.x] = 0;
    int i = blockIdx.x * 256 + threadIdx.x;        // 65536 float4s
    float4 x = ((const float4*)W1)[i];
    uint32_t hi, lo = cvt4_f16(x, hi);
    uint2 v; v.x = lo; v.y = hi;
    *(uint2*)(g_w1f + (size_t)i * 4) = v;
}

// ===================== score kernel (+ fused batch softmax/context) =====================
// CTA: 128 rows x 512 units, 1024 threads (32 warps: 4m x 8n, warp tile m32 x n32).
// nb in {0,1}: n-tile 256. K in 16 chunks of 32: B via 3-buffer cp.async ring;
// A converted fp32->fp16 chunk-by-chunk DURING nb=0 (overlapped with MMA).
#define MTILE  128
#define APITCH 520                 // fp16; 1040B row, mod 128 = 16 -> conflict-free
#define BPITCH 40                  // fp16; 80B row (64B data + pad) -> conflict-free
#define BBUF   (256*BPITCH*2)      // 20480 B per buffer

#define OFF_A    0                             // 133120 bytes
#define OFF_B    (MTILE*APITCH*2)              // 133120 ; 3 bufs -> 194560
#define OFF_BB2  (OFF_B + 3*BBUF)              // 194560 (256 u32 bias f16x2)
#define OFF_V2H  (OFF_BB2 + 1024)              // 195584
#define OFF_V2L  (OFF_V2H + 1024)              // 196608
#define OFF_HP2  (OFF_V2L + 1024)              // 197632 (2 x 256 u32)
#define OFF_CLM  (OFF_HP2 + 2048)              // 199680 (2 ints + pad)
#define OFF_RED2 (OFF_CLM + 16)                // 199696 (1024 f32, dedicated)
#define OFF_SW   OFF_B                         // claim-phase aliases over B bufs
#define OFF_SR2  (OFF_B + 4096)
#define OFF_PRT  (OFF_B + 8192)                // 8 x 512 f32
#define SMEM_BYTES (OFF_RED2 + 4096)           // 203792

__global__ void __launch_bounds__(1024, 1)
score_mma_kernel(const float* __restrict__ A,   // features [368640, 512]
                 const float* __restrict__ b1,  // [512]
                 const float* __restrict__ Vw,  // [512]
                 const float* __restrict__ Vb,  // [1]
                 float* __restrict__ out)       // [BS*DIM ctx | BS*SEQ weights]
{
    extern __shared__ char sm[];
    const uint32_t smbase = smem_u32(sm);

    const int tid  = threadIdx.x;
    const int lane = tid & 31;
    const int wid  = tid >> 5;
    const int wm   = wid & 3;       // 4 m-subtiles of 32
    const int wn   = wid >> 2;      // 8 n32 subtiles within 256-wide nb tile
    const int m0   = blockIdx.x * MTILE;
    const int bidx0 = m0 / SEQ;

    __half*   a_f    = (__half*)(sm + OFF_A);
    uint32_t* s_bb2  = (uint32_t*)(sm + OFF_BB2);
    uint32_t* s_v2h  = (uint32_t*)(sm + OFF_V2H);
    uint32_t* s_v2l  = (uint32_t*)(sm + OFF_V2L);
    uint32_t* s_hp2  = (uint32_t*)(sm + OFF_HP2);
    int*      s_clm  = (int*)(sm + OFF_CLM);
    float*    s_red2 = (float*)(sm + OFF_RED2);

    if (tid == 0) { s_clm[0] = -1; s_clm[1] = -1; }

    // ---- stage tables (f16x2 packed) ----
    if (tid < 256) {
        float2 bb = ((const float2*)b1)[tid];
        s_bb2[tid] = pkh2(bb.x, bb.y);
        float2 vv = ((const float2*)Vw)[tid];
        float vh0 = __half2float(__float2half_rn(vv.x));
        float vh1 = __half2float(__float2half_rn(vv.y));
        s_v2h[tid] = pkh2(vh0, vh1);
        s_v2l[tid] = pkh2(vv.x - vh0, vv.y - vh1);
        float2 h0 = ((const float2*)(g_hproj + (size_t)bidx0 * DIM))[tid];
        s_hp2[tid] = pkh2(h0.x, h0.y);
        float2 h1 = make_float2(0.f, 0.f);
        if (bidx0 + 1 < BS)
            h1 = ((const float2*)(g_hproj + (size_t)(bidx0 + 1) * DIM))[tid];
        s_hp2[256 + tid] = pkh2(h1.x, h1.y);
    }

    // ---- A streaming indices: 1024 threads, 1 float4 per thread per chunk ----
    const float4* Av = (const float4*)A;     // row = 128 float4
    const int ar  = tid >> 3;                // 0..127
    const int ac4 = tid & 7;                 // float4 col within 32-col chunk

    // ---- convert ONLY chunk 0 in prologue ----
    {
        float4 x0 = Av[(size_t)(m0 + ar) * 128 + ac4];
        uint32_t h, l = cvt4_f16(x0, h);
        *(uint2*)(a_f + ar * APITCH + ac4 * 4) = make_uint2(l, h);
    }
    __syncthreads();

    // ---- ldmatrix lane addresses ----
    const uint32_t a_addr0 = smbase + OFF_A +
        (uint32_t)((wm * 32 + (lane & 15)) * APITCH + (lane >> 4) * 8) * 2;

    const int b_n = (lane & 7) + ((lane >> 4) & 1) * 8;
    const int b_k = ((lane >> 3) & 1) * 8;
    const uint32_t bq = (uint32_t)((wn * 32 + b_n) * BPITCH + b_k) * 2;

    // ---- B cp.async indices: 1024 threads, 1 CPA16 per thread per chunk ----
    const int r0 = tid >> 2;                      // 0..255
    const int q  = tid & 3;                       // uint4 within 64B data
    const uint4* gw1 = (const uint4*)g_w1f;       // row = 64 uint4
    const uint32_t bst = (uint32_t)(r0 * BPITCH + q * 8) * 2;

    // ---- epilogue row info ----
    const int g = lane >> 2;
    const int t = lane & 3;
    int rowsel[2][2];
    #pragma unroll
    for (int sub = 0; sub < 2; ++sub) {
        int rl = wm * 32 + sub * 16 + g;
        rowsel[sub][0] = ((m0 + rl) / SEQ) - bidx0;
        rowsel[sub][1] = ((m0 + rl + 8) / SEQ) - bidx0;
    }

    for (int nb = 0; nb < 2; ++nb) {
        const int n0 = nb * 256;
        const int pb = nb * 128 + wn * 16 + t;    // f16x2 pair base for this warp
        const uint4* gbase = gw1 + (size_t)(n0 + r0) * 64 + q;

        float acc[2][4][4];
        #pragma unroll
        for (int sub = 0; sub < 2; ++sub)
            #pragma unroll
            for (int f = 0; f < 4; ++f)
                #pragma unroll
                for (int e = 0; e < 4; ++e) acc[sub][f][e] = 0.f;

        if (nb > 0) __syncthreads();   // protect buf reuse across nb

        // ---- preload B chunks 0,1 into bufs 0,1 (separate groups) ----
        {
            CPA16(smbase + OFF_B + bst, gbase);
            CPA_COMMIT();
            CPA16(smbase + OFF_B + BBUF + bst, gbase + 4);
            CPA_COMMIT();
        }

        for (int kc = 0; kc < 16; ++kc) {
            const int cur = kc % 3;
            const uint32_t bcur = smbase + OFF_B + (uint32_t)cur * BBUF + bq;

            CPA_WAIT1();          // B chunk kc complete (<=1 pending: kc+1)
            __syncthreads();      // B smem + A chunk kc's STS visible to all warps

            // prefetch B chunk kc+2 into buf (kc+2)%3 (always commit for accounting)
            if (kc <= 13) {
                uint32_t dst = smbase + OFF_B + (uint32_t)((kc + 2) % 3) * BBUF + bst;
                CPA16(dst, gbase + (kc + 2) * 4);
            }
            CPA_COMMIT();

            // issue A-conversion load for chunk kc+1 (nb=0 only)
            float4 ax0;
            const bool do_a = (nb == 0) && (kc < 15);
            if (do_a)
                ax0 = Av[(size_t)(m0 + ar) * 128 + (size_t)(kc + 1) * 8 + ac4];

            #pragma unroll
            for (int ks = 0; ks < 2; ++ks) {
                const uint32_t koffA = (uint32_t)(kc * 32 + ks * 16) * 2;
                const uint32_t koffB = (uint32_t)(ks * 16) * 2;
                uint32_t a[8];
                ldsm4(a,     a_addr0 + koffA);
                ldsm4(a + 4, a_addr0 + 16 * APITCH * 2 + koffA);
                uint32_t bf[8];
                ldsm4(bf,     bcur + koffB);
                ldsm4(bf + 4, bcur + 16 * BPITCH * 2 + koffB);
                #pragma unroll
                for (int f = 0; f < 4; ++f) {
                    mma16816_f16(acc[0][f], a[0], a[1], a[2], a[3], bf[2*f], bf[2*f+1]);
                    mma16816_f16(acc[1][f], a[4], a[5], a[6], a[7], bf[2*f], bf[2*f+1]);
                }
            }

            // convert + store A chunk kc+1 (published by next chunk's barrier)
            if (do_a) {
                uint32_t h, l = cvt4_f16(ax0, h);
                *(uint2*)(a_f + ar * APITCH + (kc + 1) * 32 + ac4 * 4) = make_uint2(l, h);
            }
        }

        // ---- fused epilogue: bias+relu+hp+tanh in f16x2, V-dot via tensor pipe ----
        float acc2[2][4] = {{0.f,0.f,0.f,0.f},{0.f,0.f,0.f,0.f}};
        #pragma unroll
        for (int sub = 0; sub < 2; ++sub) {
            #pragma unroll
            for (int F = 0; F < 2; ++F) {
                uint32_t tf[2][2];
                #pragma unroll
                for (int j = 0; j < 2; ++j) {
                    const int f = 2 * F + j;
                    uint32_t bb  = s_bb2[pb + f * 4];
                    uint32_t hpa = s_hp2[rowsel[sub][0] * 256 + pb + f * 4];
                    uint32_t hpb = s_hp2[rowsel[sub][1] * 256 + pb + f * 4];
                    uint32_t x0 = cvt_f16x2(acc[sub][f][1], acc[sub][f][0]);
                    uint32_t x1 = cvt_f16x2(acc[sub][f][3], acc[sub][f][2]);
                    x0 = hadd2(hmax2_0(hadd2(x0, bb)), hpa);
                    x1 = hadd2(hmax2_0(hadd2(x1, bb)), hpb);
                    tf[j][0] = htanh2(x0);
                    tf[j][1] = htanh2(x1);
                }
                uint32_t b0h = s_v2h[pb + F * 8];
                uint32_t b1h = s_v2h[pb + F * 8 + 4];
                uint32_t b0l = s_v2l[pb + F * 8];
                uint32_t b1l = s_v2l[pb + F * 8 + 4];
                mma16816_f16(acc2[sub], tf[0][0], tf[0][1], tf[1][0], tf[1][1], b0h, b1h);
                mma16816_f16(acc2[sub], tf[0][0], tf[0][1], tf[1][0], tf[1][1], b0l, b1l);
            }
        }
        // flush per-nb V-dot partials into dedicated smem (same thread both nb -> no race)
        if (t == 0) {
            #pragma unroll
            for (int sub = 0; sub < 2; ++sub) {
                int rl = wm * 32 + sub * 16 + g;
                if (nb == 0) {
                    s_red2[wn * 128 + rl]     = acc2[sub][0];
                    s_red2[wn * 128 + rl + 8] = acc2[sub][2];
                } else {
                    s_red2[wn * 128 + rl]     += acc2[sub][0];
                    s_red2[wn * 128 + rl + 8] += acc2[sub][2];
                }
            }
        }
    }

    __syncthreads();   // s_red2 complete; B buffers dead
    if (tid < 128) {
        float s = 0.f;
        #pragma unroll
        for (int k = 0; k < 8; ++k) s += s_red2[k * 128 + tid];  // fixed order
        g_score[m0 + tid] = s + Vb[0];
    }

    // ============ fused per-batch softmax + context (claim protocol) ============
    __threadfence();
    __syncthreads();

    const int b_last = (m0 + MTILE - 1) / SEQ;
    if (tid == 0) {
        int idx = 0;
        for (int b = bidx0; b <= b_last && b < BS; ++b) {
            int cov = ((SEQ * (b + 1) - 1) >> 7) - ((SEQ * b) >> 7) + 1;
            int old = atomicAdd(&g_cnt[b], 1);
            if (old == cov - 1) s_clm[idx++] = b;
        }
    }
    __syncthreads();

    float* sw   = (float*)(sm + OFF_SW);
    float* sr2  = (float*)(sm + OFF_SR2);
    float* part = (float*)(sm + OFF_PRT);

    #pragma unroll 1
    for (int ci = 0; ci < 2; ++ci) {
        const int b = s_clm[ci];
        if (b < 0) continue;

        float sc = (tid < SEQ) ? __ldcg(&g_score[b * SEQ + tid]) : -3.4e38f;
        sr2[tid] = sc;
        __syncthreads();
        #pragma unroll
        for (int off = 512; off > 0; off >>= 1) {
            if (tid < off) sr2[tid] = fmaxf(sr2[tid], sr2[tid + off]);
            __syncthreads();
        }
        float mx = sr2[0];
        __syncthreads();

        float e = (tid < SEQ) ? expf(sc - mx) : 0.f;
        sr2[tid] = e;
        __syncthreads();
        #pragma unroll
        for (int off = 512; off > 0; off >>= 1) {
            if (tid < off) sr2[tid] += sr2[tid + off];
            __syncthreads();
        }
        float inv = 1.f / sr2[0];

        float wt = e * inv;
        if (tid < SEQ) {
            sw[tid] = wt;
            out[(size_t)BS * DIM + (size_t)b * SEQ + tid] = wt;
        }
        __syncthreads();

        // context: 8 s-groups x 128 threads, each owns 4 consecutive e (float4)
        const int sg = tid >> 7;            // 0..7
        const int e4 = tid & 127;
        const float4* fb = (const float4*)(A + (size_t)b * SEQ * DIM);
        float4 acc = make_float4(0.f, 0.f, 0.f, 0.f);
        const int sBeg = sg * 45, sEnd = sBeg + 45;
        #pragma unroll 5
        for (int s = sBeg; s < sEnd; ++s) {
            float ws = sw[s];
            float4 v = fb[(size_t)s * 128 + e4];
            acc.x += ws * v.x; acc.y += ws * v.y;
            acc.z += ws * v.z; acc.w += ws * v.w;
        }
        ((float4*)(part + sg * 512))[e4] = acc;
        __syncthreads();

        if (tid < 512) {
            float r = ((part[tid] + part[512 + tid]) + (part[1024 + tid] + part[1536 + tid]))
                    + ((part[2048 + tid] + part[2560 + tid]) + (part[3072 + tid] + part[3584 + tid]));
            out[(size_t)b * DIM + tid] = r;
        }
        __syncthreads();
    }
}

// ===================== hproj kernel: 64x64 tiles, 128 CTAs =====================
__global__ void __launch_bounds__(256) hproj_kernel(
    const float* __restrict__ A,    // hidden [1024,512]
    const float* __restrict__ B,    // W2_w   [512,512]
    const float* __restrict__ bias) // W2_b   [512]
{
    __shared__ float As[16][68];
    __shared__ float Bs[16][68];

    const int tid = threadIdx.x;
    const int tx  = tid & 15;
    const int ty  = tid >> 4;
    const int m0  = blockIdx.x * 64;
    const int n0  = blockIdx.y * 64;

    float acc[4][4];
    #pragma unroll
    for (int i = 0; i < 4; ++i)
        #pragma unroll
        for (int j = 0; j < 4; ++j) acc[i][j] = 0.f;

    const int lrow = tid >> 2, lseg = tid & 3;

    for (int kk = 0; kk < DIM; kk += 16) {
        __syncthreads();
        float4 v = *reinterpret_cast<const float4*>(A + (size_t)(m0 + lrow) * DIM + kk + lseg * 4);
        As[lseg*4+0][lrow] = v.x; As[lseg*4+1][lrow] = v.y;
        As[lseg*4+2][lrow] = v.z; As[lseg*4+3][lrow] = v.w;
        float4 w = *reinterpret_cast<const float4*>(B + (size_t)(n0 + lrow) * DIM + kk + lseg * 4);
        Bs[lseg*4+0][lrow] = w.x; Bs[lseg*4+1][lrow] = w.y;
        Bs[lseg*4+2][lrow] = w.z; Bs[lseg*4+3][lrow] = w.w;
        __syncthreads();
        #pragma unroll
        for (int k = 0; k < 16; ++k) {
            float4 a4 = *reinterpret_cast<const float4*>(&As[k][ty * 4]);
            float4 b4 = *reinterpret_cast<const float4*>(&Bs[k][tx * 4]);
            float a[4] = {a4.x, a4.y, a4.z, a4.w};
            float b[4] = {b4.x, b4.y, b4.z, b4.w};
            #pragma unroll
            for (int i = 0; i < 4; ++i)
                #pragma unroll
                for (int j = 0; j < 4; ++j)
                    acc[i][j] += a[i] * b[j];
        }
    }

    #pragma unroll
    for (int i = 0; i < 4; ++i) {
        int m = m0 + ty * 4 + i;
        #pragma unroll
        for (int j = 0; j < 4; ++j) {
            int n = n0 + tx * 4 + j;
            float v = acc[i][j] + bias[n];
            g_hproj[(size_t)m * DIM + n] = v > 0.f ? v : 0.f;
        }
    }
}

// ===================== launch =====================
extern "C" void kernel_launch(void* const* d_in, const int* in_sizes, int n_in,
                              void* d_out, int out_size)
{
    const float* hidden   = (const float*)d_in[0];
    const float* features = (const float*)d_in[1];
    const float* W1_w     = (const float*)d_in[2];
    const float* W1_b     = (const float*)d_in[3];
    const float* W2_w     = (const float*)d_in[4];
    const float* W2_b     = (const float*)d_in[5];
    const float* V_w      = (const float*)d_in[6];
    const float* V_b      = (const float*)d_in[7];
    float* out = (float*)d_out;

    cudaFuncSetAttribute(score_mma_kernel,
                         cudaFuncAttributeMaxDynamicSharedMemorySize, SMEM_BYTES);

    prep_w1_kernel<<<256, 256>>>(W1_w);
    hproj_kernel<<<dim3(16, 8), 256>>>(hidden, W2_w, W2_b);
    score_mma_kernel<<<MTOT / MTILE, 1024, SMEM_BYTES>>>(features, W1_b, V_w, V_b, out);
}

// round 13
// speedup vs baseline: 1.6372x; 1.6372x over previous
#include <cuda_runtime.h>
#include <cuda_fp16.h>
#include <math.h>
#include <stdint.h>

#define BS   1024
#define SEQ  360
#define DIM  512
#define MTOT (BS*SEQ)

// ===================== scratch =====================
__device__ float g_hproj[BS * DIM];          // relu(hidden @ W2^T + b2)
__device__ float g_score[BS * SEQ];          // pre-softmax scores
__device__ __half g_w1f[DIM * DIM];          // W1 fp16
__device__ int   g_cnt[BS];                  // per-batch CTA completion counters

// ===================== helpers =====================
__device__ __forceinline__ uint32_t smem_u32(const void* p) {
    uint32_t a;
    asm("{ .reg .u64 t; cvta.to.shared.u64 t, %1; cvt.u32.u64 %0, t; }" : "=r"(a) : "l"(p));
    return a;
}
__device__ __forceinline__ void ldsm4(uint32_t* r, uint32_t addr) {
    asm volatile("ldmatrix.sync.aligned.m8n8.x4.shared.b16 {%0,%1,%2,%3}, [%4];"
                 : "=r"(r[0]), "=r"(r[1]), "=r"(r[2]), "=r"(r[3]) : "r"(addr));
}
__device__ __forceinline__ void mma16816_f16(float* c, uint32_t a0, uint32_t a1,
                                             uint32_t a2, uint32_t a3,
                                             uint32_t b0, uint32_t b1) {
    asm volatile("mma.sync.aligned.m16n8k16.row.col.f32.f16.f16.f32 "
                 "{%0,%1,%2,%3}, {%4,%5,%6,%7}, {%8,%9}, {%0,%1,%2,%3};"
                 : "+f"(c[0]), "+f"(c[1]), "+f"(c[2]), "+f"(c[3])
                 : "r"(a0), "r"(a1), "r"(a2), "r"(a3), "r"(b0), "r"(b1));
}
#define CPA16(smaddr, gptr) \
    asm volatile("cp.async.cg.shared.global [%0], [%1], 16;" :: "r"(smaddr), "l"(gptr))
#define CPA_COMMIT() asm volatile("cp.async.commit_group;" ::: "memory")
#define CPA_WAIT1()  asm volatile("cp.async.wait_group 1;" ::: "memory")

__device__ __forceinline__ uint32_t cvt_f16x2(float hi, float lo) {
    uint32_t d; asm("cvt.rn.f16x2.f32 %0, %1, %2;" : "=r"(d) : "f"(hi), "f"(lo)); return d;
}
__device__ __forceinline__ uint32_t hmax2_0(uint32_t x) {
    uint32_t d; asm("max.f16x2 %0, %1, %2;" : "=r"(d) : "r"(x), "r"(0u)); return d;
}
__device__ __forceinline__ uint32_t hadd2(uint32_t a, uint32_t b) {
    uint32_t d; asm("add.f16x2 %0, %1, %2;" : "=r"(d) : "r"(a), "r"(b)); return d;
}
__device__ __forceinline__ uint32_t htanh2(uint32_t x) {
    uint32_t d; asm("tanh.approx.f16x2 %0, %1;" : "=r"(d) : "r"(x)); return d;
}
__device__ __forceinline__ uint32_t pkh2(float lo, float hi) {
    __half2 h = __floats2half2_rn(lo, hi);   // .x = lo
    return *(uint32_t*)&h;
}
__device__ __forceinline__ uint32_t cvt4_f16(float4 x, uint32_t& hi2) {
    hi2 = pkh2(x.z, x.w);
    return pkh2(x.x, x.y);
}

// ===================== prep: W1 -> fp16 + zero batch counters =====================
__global__ void __launch_bounds__(256) prep_w1_kernel(const float* __restrict__ W1) {
    if (blockIdx.x < 4) g_cnt[blockIdx.x * 256 + threadIdx.x] = 0;
    int i = blockIdx.x * 256 + threadIdx.x;        // 65536 float4s
    float4 x = ((const float4*)W1)[i];
    uint32_t hi, lo = cvt4_f16(x, hi);
    uint2 v; v.x = lo; v.y = hi;
    *(uint2*)(g_w1f + (size_t)i * 4) = v;
}

// ===================== score kernel (+ fused batch softmax/context) =====================
// CTA: 128 rows x 512 units, 512 threads (16 warps: 4m x 4n), 1 CTA/SM.
// nb in {0,1}: n-tile 256. K in 16 chunks of 32: B via 3-buffer cp.async ring;
// A converted fp32->fp16 chunk-by-chunk DURING nb=0 (overlapped with MMA).
// After scores: last CTA covering a batch claims it and runs softmax+context.
#define MTILE  128
#define APITCH 520                 // fp16; 1040B row, mod 128 = 16 -> conflict-free
#define BPITCH 40                  // fp16; 80B row -> conflict-free ldmatrix
#define BBUF   (256*BPITCH*2)      // 20480 B per buffer

#define OFF_A   0                              // 133120 bytes
#define OFF_B   (MTILE*APITCH*2)               // 133120 ; 3 bufs
#define OFF_BB2 (OFF_B + 3*BBUF)               // 194560 (256 u32 bias f16x2)
#define OFF_V2H (OFF_BB2 + 1024)               // 195584
#define OFF_V2L (OFF_V2H + 1024)               // 196608
#define OFF_HP2 (OFF_V2L + 1024)               // 197632 (2 x 256 u32)
#define OFF_CLM (OFF_HP2 + 2048)               // 199680 (2 ints)
#define OFF_RED OFF_B                          // s_red aliased over B bufs (512 f32)
#define OFF_SW  (OFF_B + 2048)                 // softmax weights (360 f32)
#define OFF_SR2 (OFF_B + 4096)                 // softmax reduce (512 f32)
#define OFF_PRT (OFF_B + 6144)                 // context partials (4x512 f32)
#define SMEM_BYTES (OFF_CLM + 16)              // 199696

__global__ void __launch_bounds__(512, 1)
score_mma_kernel(const float* __restrict__ A,   // features [368640, 512]
                 const float* __restrict__ b1,  // [512]
                 const float* __restrict__ Vw,  // [512]
                 const float* __restrict__ Vb,  // [1]
                 float* __restrict__ out)       // [BS*DIM ctx | BS*SEQ weights]
{
    extern __shared__ char sm[];
    const uint32_t smbase = smem_u32(sm);

    const int tid  = threadIdx.x;
    const int lane = tid & 31;
    const int wid  = tid >> 5;
    const int wm   = wid & 3;       // 4 m-subtiles of 32
    const int wn   = wid >> 2;      // 4 n64 subtiles within 256-wide nb tile
    const int m0   = blockIdx.x * MTILE;
    const int bidx0 = m0 / SEQ;

    __half*   a_f   = (__half*)(sm + OFF_A);
    uint32_t* s_bb2 = (uint32_t*)(sm + OFF_BB2);
    uint32_t* s_v2h = (uint32_t*)(sm + OFF_V2H);
    uint32_t* s_v2l = (uint32_t*)(sm + OFF_V2L);
    uint32_t* s_hp2 = (uint32_t*)(sm + OFF_HP2);
    int*      s_clm = (int*)(sm + OFF_CLM);

    if (tid == 0) { s_clm[0] = -1; s_clm[1] = -1; }

    // ---- stage tables (f16x2 packed) ----
    if (tid < 256) {
        float2 bb = ((const float2*)b1)[tid];
        s_bb2[tid] = pkh2(bb.x, bb.y);
        float2 vv = ((const float2*)Vw)[tid];
        float vh0 = __half2float(__float2half_rn(vv.x));
        float vh1 = __half2float(__float2half_rn(vv.y));
        s_v2h[tid] = pkh2(vh0, vh1);
        s_v2l[tid] = pkh2(vv.x - vh0, vv.y - vh1);
        float2 h0 = __ldg((const float2*)(g_hproj + (size_t)bidx0 * DIM) + tid);
        s_hp2[tid] = pkh2(h0.x, h0.y);
        float2 h1 = make_float2(0.f, 0.f);
        if (bidx0 + 1 < BS)
            h1 = __ldg((const float2*)(g_hproj + (size_t)(bidx0 + 1) * DIM) + tid);
        s_hp2[256 + tid] = pkh2(h1.x, h1.y);
    }

    // ---- A streaming-conversion indices: thread owns 2 float4 per chunk ----
    const float4* Av = (const float4*)A;     // row = 128 float4
    const int ar  = tid >> 3;                // 0..63 (and ar+64)
    const int ac4 = tid & 7;                 // float4 col within 32-col chunk

    // ---- convert ONLY chunk 0 in prologue (rest streamed in nb=0 loop) ----
    {
        float4 x0 = Av[(size_t)(m0 + ar) * 128 + ac4];
        float4 x1 = Av[(size_t)(m0 + ar + 64) * 128 + ac4];
        uint32_t h, l;
        l = cvt4_f16(x0, h);
        *(uint2*)(a_f + ar * APITCH + ac4 * 4) = make_uint2(l, h);
        l = cvt4_f16(x1, h);
        *(uint2*)(a_f + (ar + 64) * APITCH + ac4 * 4) = make_uint2(l, h);
    }
    __syncthreads();

    // ---- ldmatrix lane addresses ----
    const uint32_t a_addr0 = smbase + OFF_A +
        (uint32_t)((wm * 32 + (lane & 15)) * APITCH + (lane >> 4) * 8) * 2;
    const uint32_t a_addr1 = a_addr0 + 16 * APITCH * 2;

    const int b_n = (lane & 7) + ((lane >> 4) & 1) * 8;
    const int b_k = ((lane >> 3) & 1) * 8;
    const uint32_t bq = (uint32_t)((wn * 64 + b_n) * BPITCH + b_k) * 2;
    uint32_t b_addr[3];
    b_addr[0] = smbase + OFF_B + bq;
    b_addr[1] = b_addr[0] + BBUF;
    b_addr[2] = b_addr[1] + BBUF;

    // ---- B cp.async indices: 512 threads, 2 threads per row, 32B each ----
    const int r0 = tid >> 1;                      // 0..255
    const int jj = (tid & 1) * 2;                 // uint4 pair within row
    const uint4* gw1 = (const uint4*)g_w1f;       // row = 64 uint4
    const uint32_t bst = (uint32_t)(r0 * BPITCH + jj * 8) * 2;   // smem offset within buffer

    // ---- epilogue row info ----
    const int g = lane >> 2;
    const int t = lane & 3;
    int rowsel[2][2];
    #pragma unroll
    for (int sub = 0; sub < 2; ++sub) {
        int rl = wm * 32 + sub * 16 + g;
        rowsel[sub][0] = ((m0 + rl) / SEQ) - bidx0;
        rowsel[sub][1] = ((m0 + rl + 8) / SEQ) - bidx0;
    }

    float acc2[2][4] = {{0.f,0.f,0.f,0.f},{0.f,0.f,0.f,0.f}};

    for (int nb = 0; nb < 2; ++nb) {
        const int n0 = nb * 256;
        const int pb = nb * 128 + wn * 32 + t;    // f16x2 pair base for this warp
        const uint4* gbase = gw1 + (size_t)(n0 + r0) * 64 + jj;

        float acc[2][8][4];
        #pragma unroll
        for (int sub = 0; sub < 2; ++sub)
            #pragma unroll
            for (int f = 0; f < 8; ++f)
                #pragma unroll
                for (int e = 0; e < 4; ++e) acc[sub][f][e] = 0.f;

        if (nb > 0) __syncthreads();   // protect buf reuse across nb

        // ---- preload B chunks 0,1 into bufs 0,1 (separate groups) ----
        {
            uint32_t s0 = smbase + OFF_B + bst;
            CPA16(s0, gbase); CPA16(s0 + 16, gbase + 1);
            CPA_COMMIT();
            uint32_t s1 = smbase + OFF_B + BBUF + bst;
            CPA16(s1, gbase + 4); CPA16(s1 + 16, gbase + 5);
            CPA_COMMIT();
        }

        for (int kc = 0; kc < 16; ++kc) {
            const int cur = kc % 3;

            CPA_WAIT1();          // B chunk kc complete (<=1 pending: kc+1)
            __syncthreads();      // B smem + A chunk kc's STS visible to all warps

            // prefetch B chunk kc+2 into buf (kc+2)%3 (always commit for accounting)
            if (kc <= 13) {
                uint32_t dst = smbase + OFF_B + (uint32_t)((kc + 2) % 3) * BBUF + bst;
                const uint4* gp = gbase + (kc + 2) * 4;
                CPA16(dst, gp); CPA16(dst + 16, gp + 1);
            }
            CPA_COMMIT();

            // issue A-conversion loads for chunk kc+1 (nb=0 only)
            float4 ax0, ax1;
            const bool do_a = (nb == 0) && (kc < 15);
            if (do_a) {
                const size_t gofs = (size_t)(kc + 1) * 8 + ac4;
                ax0 = Av[(size_t)(m0 + ar) * 128 + gofs];
                ax1 = Av[(size_t)(m0 + ar + 64) * 128 + gofs];
            }

            #pragma unroll
            for (int ks = 0; ks < 2; ++ks) {
                const uint32_t koffA = (uint32_t)(kc * 32 + ks * 16) * 2;
                const uint32_t koffB = (uint32_t)(ks * 16) * 2;
                uint32_t a[8];
                ldsm4(a,     a_addr0 + koffA);
                ldsm4(a + 4, a_addr1 + koffA);
                #pragma unroll
                for (int half = 0; half < 2; ++half) {
                    const uint32_t hb = (uint32_t)(half * 32 * BPITCH) * 2;
                    uint32_t bf[8];
                    ldsm4(bf,     b_addr[cur] + hb + koffB);
                    ldsm4(bf + 4, b_addr[cur] + hb + 16 * BPITCH * 2 + koffB);
                    #pragma unroll
                    for (int f2 = 0; f2 < 4; ++f2) {
                        const int f = half * 4 + f2;
                        mma16816_f16(acc[0][f], a[0], a[1], a[2], a[3], bf[2*f2], bf[2*f2+1]);
                        mma16816_f16(acc[1][f], a[4], a[5], a[6], a[7], bf[2*f2], bf[2*f2+1]);
                    }
                }
            }

            // convert + store A chunk kc+1 (published by next chunk's barrier)
            if (do_a) {
                const int so = (kc + 1) * 32 + ac4 * 4;
                uint32_t h, l;
                l = cvt4_f16(ax0, h);
                *(uint2*)(a_f + ar * APITCH + so) = make_uint2(l, h);
                l = cvt4_f16(ax1, h);
                *(uint2*)(a_f + (ar + 64) * APITCH + so) = make_uint2(l, h);
            }
        }

        // ---- fused epilogue: bias+relu+hp+tanh in f16x2, V-dot via tensor pipe ----
        #pragma unroll
        for (int sub = 0; sub < 2; ++sub) {
            #pragma unroll
            for (int F = 0; F < 4; ++F) {
                uint32_t tf[2][2];
                #pragma unroll
                for (int j = 0; j < 2; ++j) {
                    const int f = 2 * F + j;
                    uint32_t bb  = s_bb2[pb + f * 4];
                    uint32_t hpa = s_hp2[rowsel[sub][0] * 256 + pb + f * 4];
                    uint32_t hpb = s_hp2[rowsel[sub][1] * 256 + pb + f * 4];
                    uint32_t x0 = cvt_f16x2(acc[sub][f][1], acc[sub][f][0]);
                    uint32_t x1 = cvt_f16x2(acc[sub][f][3], acc[sub][f][2]);
                    x0 = hadd2(hmax2_0(hadd2(x0, bb)), hpa);
                    x1 = hadd2(hmax2_0(hadd2(x1, bb)), hpb);
                    tf[j][0] = htanh2(x0);
                    tf[j][1] = htanh2(x1);
                }
                uint32_t b0h = s_v2h[pb + F * 8];
                uint32_t b1h = s_v2h[pb + F * 8 + 4];
                uint32_t b0l = s_v2l[pb + F * 8];
                uint32_t b1l = s_v2l[pb + F * 8 + 4];
                mma16816_f16(acc2[sub], tf[0][0], tf[0][1], tf[1][0], tf[1][1], b0h, b1h);
                mma16816_f16(acc2[sub], tf[0][0], tf[0][1], tf[1][0], tf[1][1], b0l, b1l);
            }
        }
    }

    // ---- deterministic final score reduction (s_red aliased over B buffers) ----
    float* s_red = (float*)(sm + OFF_RED);
    __syncthreads();   // B buffers fully dead
    if (t == 0) {
        #pragma unroll
        for (int sub = 0; sub < 2; ++sub) {
            int rl = wm * 32 + sub * 16 + g;
            s_red[wn * 128 + rl]     = acc2[sub][0];   // row rl
            s_red[wn * 128 + rl + 8] = acc2[sub][2];   // row rl+8
        }
    }
    __syncthreads();
    if (tid < 128)
        g_score[m0 + tid] = ((s_red[tid] + s_red[128 + tid]) +
                             (s_red[256 + tid] + s_red[384 + tid])) + Vb[0];

    // ============ fused per-batch softmax + context (claim protocol) ============
    __threadfence();      // order score stores before counter increments
    __syncthreads();

    const int b_last = (m0 + MTILE - 1) / SEQ;
    if (tid == 0) {
        int idx = 0;
        for (int b = bidx0; b <= b_last && b < BS; ++b) {
            int cov = ((SEQ * (b + 1) - 1) >> 7) - ((SEQ * b) >> 7) + 1;
            int old = atomicAdd(&g_cnt[b], 1);
            if (old == cov - 1) s_clm[idx++] = b;
        }
    }
    __syncthreads();

    float* sw   = (float*)(sm + OFF_SW);
    float* sr2  = (float*)(sm + OFF_SR2);
    float* part = (float*)(sm + OFF_PRT);

    #pragma unroll 1
    for (int ci = 0; ci < 2; ++ci) {
        const int b = s_clm[ci];
        if (b < 0) continue;

        float sc = (tid < SEQ) ? __ldcg(&g_score[b * SEQ + tid]) : -3.4e38f;
        sr2[tid] = sc;
        __syncthreads();
        #pragma unroll
        for (int off = 256; off > 0; off >>= 1) {
            if (tid < off) sr2[tid] = fmaxf(sr2[tid], sr2[tid + off]);
            __syncthreads();
        }
        float mx = sr2[0];
        __syncthreads();

        float e = (tid < SEQ) ? __expf(sc - mx) : 0.f;
        sr2[tid] = e;
        __syncthreads();
        #pragma unroll
        for (int off = 256; off > 0; off >>= 1) {
            if (tid < off) sr2[tid] += sr2[tid + off];
            __syncthreads();
        }
        float inv = 1.f / sr2[0];

        float wt = e * inv;
        if (tid < SEQ) {
            sw[tid] = wt;
            out[(size_t)BS * DIM + (size_t)b * SEQ + tid] = wt;
        }
        __syncthreads();

        // context: 4 s-groups x 128 threads, each owns 4 consecutive e (float4)
        const int sg = tid >> 7;
        const int e4 = tid & 127;
        const float4* fb = (const float4*)(A + (size_t)b * SEQ * DIM);
        float4 acc = make_float4(0.f, 0.f, 0.f, 0.f);
        const int sBeg = sg * 90, sEnd = sBeg + 90;
        #pragma unroll 5
        for (int s = sBeg; s < sEnd; ++s) {
            float ws = sw[s];
            float4 v = fb[(size_t)s * 128 + e4];
            acc.x += ws * v.x; acc.y += ws * v.y;
            acc.z += ws * v.z; acc.w += ws * v.w;
        }
        ((float4*)(part + sg * 512))[e4] = acc;
        __syncthreads();

        float r = (part[tid] + part[512 + tid]) + (part[1024 + tid] + part[1536 + tid]);
        out[(size_t)b * DIM + tid] = r;
        __syncthreads();
    }
}

// ===================== hproj kernel: 64x64 tiles, 128 CTAs =====================
__global__ void __launch_bounds__(256) hproj_kernel(
    const float* __restrict__ A,    // hidden [1024,512]
    const float* __restrict__ B,    // W2_w   [512,512]
    const float* __restrict__ bias) // W2_b   [512]
{
    __shared__ float As[16][68];
    __shared__ float Bs[16][68];

    const int tid = threadIdx.x;
    const int tx  = tid & 15;
    const int ty  = tid >> 4;
    const int m0  = blockIdx.x * 64;
    const int n0  = blockIdx.y * 64;

    float acc[4][4];
    #pragma unroll
    for (int i = 0; i < 4; ++i)
        #pragma unroll
        for (int j = 0; j < 4; ++j) acc[i][j] = 0.f;

    const int lrow = tid >> 2, lseg = tid & 3;

    for (int kk = 0; kk < DIM; kk += 16) {
        __syncthreads();
        float4 v = *reinterpret_cast<const float4*>(A + (size_t)(m0 + lrow) * DIM + kk + lseg * 4);
        As[lseg*4+0][lrow] = v.x; As[lseg*4+1][lrow] = v.y;
        As[lseg*4+2][lrow] = v.z; As[lseg*4+3][lrow] = v.w;
        float4 w = *reinterpret_cast<const float4*>(B + (size_t)(n0 + lrow) * DIM + kk + lseg * 4);
        Bs[lseg*4+0][lrow] = w.x; Bs[lseg*4+1][lrow] = w.y;
        Bs[lseg*4+2][lrow] = w.z; Bs[lseg*4+3][lrow] = w.w;
        __syncthreads();
        #pragma unroll
        for (int k = 0; k < 16; ++k) {
            float4 a4 = *reinterpret_cast<const float4*>(&As[k][ty * 4]);
            float4 b4 = *reinterpret_cast<const float4*>(&Bs[k][tx * 4]);
            float a[4] = {a4.x, a4.y, a4.z, a4.w};
            float b[4] = {b4.x, b4.y, b4.z, b4.w};
            #pragma unroll
            for (int i = 0; i < 4; ++i)
                #pragma unroll
                for (int j = 0; j < 4; ++j)
                    acc[i][j] += a[i] * b[j];
        }
    }

    #pragma unroll
    for (int i = 0; i < 4; ++i) {
        int m = m0 + ty * 4 + i;
        #pragma unroll
        for (int j = 0; j < 4; ++j) {
            int n = n0 + tx * 4 + j;
            float v = acc[i][j] + bias[n];
            g_hproj[(size_t)m * DIM + n] = v > 0.f ? v : 0.f;
        }
    }
}

// ===================== launch =====================
extern "C" void kernel_launch(void* const* d_in, const int* in_sizes, int n_in,
                              void* d_out, int out_size)
{
    const float* hidden   = (const float*)d_in[0];
    const float* features = (const float*)d_in[1];
    const float* W1_w     = (const float*)d_in[2];
    const float* W1_b     = (const float*)d_in[3];
    const float* W2_w     = (const float*)d_in[4];
    const float* W2_b     = (const float*)d_in[5];
    const float* V_w      = (const float*)d_in[6];
    const float* V_b      = (const float*)d_in[7];
    float* out = (float*)d_out;

    cudaFuncSetAttribute(score_mma_kernel,
                         cudaFuncAttributeMaxDynamicSharedMemorySize, SMEM_BYTES);

    prep_w1_kernel<<<256, 256>>>(W1_w);
    hproj_kernel<<<dim3(16, 8), 256>>>(hidden, W2_w, W2_b);
    score_mma_kernel<<<MTOT / MTILE, 512, SMEM_BYTES>>>(features, W1_b, V_w, V_b, out);
}

// round 15
// speedup vs baseline: 1.6474x; 1.0063x over previous
#include <cuda_runtime.h>
#include <cuda_fp16.h>
#include <math.h>
#include <stdint.h>

#define BS   1024
#define SEQ  360
#define DIM  512
#define MTOT (BS*SEQ)

// ===================== scratch =====================
__device__ float g_hproj[BS * DIM];          // relu(hidden @ W2^T + b2)
__device__ float g_score[BS * SEQ];          // pre-softmax scores
__device__ __half g_w1f[DIM * DIM];          // W1 fp16
__device__ int   g_cnt[BS];                  // per-batch CTA completion counters

// ===================== helpers =====================
__device__ __forceinline__ uint32_t smem_u32(const void* p) {
    uint32_t a;
    asm("{ .reg .u64 t; cvta.to.shared.u64 t, %1; cvt.u32.u64 %0, t; }" : "=r"(a) : "l"(p));
    return a;
}
__device__ __forceinline__ void ldsm4(uint32_t* r, uint32_t addr) {
    asm volatile("ldmatrix.sync.aligned.m8n8.x4.shared.b16 {%0,%1,%2,%3}, [%4];"
                 : "=r"(r[0]), "=r"(r[1]), "=r"(r[2]), "=r"(r[3]) : "r"(addr));
}
__device__ __forceinline__ void mma16816_f16(float* c, uint32_t a0, uint32_t a1,
                                             uint32_t a2, uint32_t a3,
                                             uint32_t b0, uint32_t b1) {
    asm volatile("mma.sync.aligned.m16n8k16.row.col.f32.f16.f16.f32 "
                 "{%0,%1,%2,%3}, {%4,%5,%6,%7}, {%8,%9}, {%0,%1,%2,%3};"
                 : "+f"(c[0]), "+f"(c[1]), "+f"(c[2]), "+f"(c[3])
                 : "r"(a0), "r"(a1), "r"(a2), "r"(a3), "r"(b0), "r"(b1));
}
#define CPA16(smaddr, gptr) \
    asm volatile("cp.async.cg.shared.global [%0], [%1], 16;" :: "r"(smaddr), "l"(gptr))
#define CPA_COMMIT() asm volatile("cp.async.commit_group;" ::: "memory")
#define CPA_WAIT1()  asm volatile("cp.async.wait_group 1;" ::: "memory")

__device__ __forceinline__ uint32_t cvt_f16x2(float hi, float lo) {
    uint32_t d; asm("cvt.rn.f16x2.f32 %0, %1, %2;" : "=r"(d) : "f"(hi), "f"(lo)); return d;
}
__device__ __forceinline__ uint32_t hmax2_0(uint32_t x) {
    uint32_t d; asm("max.f16x2 %0, %1, %2;" : "=r"(d) : "r"(x), "r"(0u)); return d;
}
__device__ __forceinline__ uint32_t hadd2(uint32_t a, uint32_t b) {
    uint32_t d; asm("add.f16x2 %0, %1, %2;" : "=r"(d) : "r"(a), "r"(b)); return d;
}
__device__ __forceinline__ uint32_t htanh2(uint32_t x) {
    uint32_t d; asm("tanh.approx.f16x2 %0, %1;" : "=r"(d) : "r"(x)); return d;
}
__device__ __forceinline__ uint32_t pkh2(float lo, float hi) {
    __half2 h = __floats2half2_rn(lo, hi);   // .x = lo
    return *(uint32_t*)&h;
}
__device__ __forceinline__ uint32_t cvt4_f16(float4 x, uint32_t& hi2) {
    hi2 = pkh2(x.z, x.w);
    return pkh2(x.x, x.y);
}

// ===================== prep: W1 -> fp16 + zero batch counters =====================
__global__ void __launch_bounds__(256) prep_w1_kernel(const float* __restrict__ W1) {
    if (blockIdx.x < 4) g_cnt[blockIdx.x * 256 + threadIdx.x] = 0;
    int i = blockIdx.x * 256 + threadIdx.x;        // 65536 float4s
    float4 x = ((const float4*)W1)[i];
    uint32_t hi, lo = cvt4_f16(x, hi);
    uint2 v; v.x = lo; v.y = hi;
    *(uint2*)(g_w1f + (size_t)i * 4) = v;
}

// ===================== score kernel (+ fused batch softmax/context) =====================
// CTA: 128 rows x 512 units, 512 threads (16 warps: 4m x 4n), 1 CTA/SM.
// nb in {0,1}: n-tile 256. K in 16 chunks of 32: B via 3-buffer cp.async ring;
// A converted fp32->fp16 chunk-by-chunk DURING nb=0 (overlapped with MMA).
// nb=1 B preload is issued BEFORE nb=0's epilogue (overlap load with tanh/V-dot).
// After scores: last CTA covering a batch claims it and runs softmax+context.
#define MTILE  128
#define APITCH 520                 // fp16; 1040B row, mod 128 = 16 -> conflict-free
#define BPITCH 40                  // fp16; 80B row -> conflict-free ldmatrix
#define BBUF   (256*BPITCH*2)      // 20480 B per buffer

#define OFF_A   0                              // 133120 bytes
#define OFF_B   (MTILE*APITCH*2)               // 133120 ; 3 bufs
#define OFF_BB2 (OFF_B + 3*BBUF)               // 194560 (256 u32 bias f16x2)
#define OFF_V2H (OFF_BB2 + 1024)               // 195584
#define OFF_V2L (OFF_V2H + 1024)               // 196608
#define OFF_HP2 (OFF_V2L + 1024)               // 197632 (2 x 256 u32)
#define OFF_CLM (OFF_HP2 + 2048)               // 199680 (2 ints)
#define OFF_RED OFF_B                          // s_red aliased over B bufs (512 f32)
#define OFF_SW  (OFF_B + 2048)                 // softmax weights (360 f32)
#define OFF_SR2 (OFF_B + 4096)                 // softmax reduce (512 f32)
#define OFF_PRT (OFF_B + 6144)                 // context partials (4x512 f32)
#define SMEM_BYTES (OFF_CLM + 16)              // 199696

__global__ void __launch_bounds__(512, 1)
score_mma_kernel(const float* __restrict__ A,   // features [368640, 512]
                 const float* __restrict__ b1,  // [512]
                 const float* __restrict__ Vw,  // [512]
                 const float* __restrict__ Vb,  // [1]
                 float* __restrict__ out)       // [BS*DIM ctx | BS*SEQ weights]
{
    extern __shared__ char sm[];
    const uint32_t smbase = smem_u32(sm);

    const int tid  = threadIdx.x;
    const int lane = tid & 31;
    const int wid  = tid >> 5;
    const int wm   = wid & 3;       // 4 m-subtiles of 32
    const int wn   = wid >> 2;      // 4 n64 subtiles within 256-wide nb tile
    const int m0   = blockIdx.x * MTILE;
    const int bidx0 = m0 / SEQ;

    __half*   a_f   = (__half*)(sm + OFF_A);
    uint32_t* s_bb2 = (uint32_t*)(sm + OFF_BB2);
    uint32_t* s_v2h = (uint32_t*)(sm + OFF_V2H);
    uint32_t* s_v2l = (uint32_t*)(sm + OFF_V2L);
    uint32_t* s_hp2 = (uint32_t*)(sm + OFF_HP2);
    int*      s_clm = (int*)(sm + OFF_CLM);

    if (tid == 0) { s_clm[0] = -1; s_clm[1] = -1; }

    // ---- stage tables (f16x2 packed) ----
    if (tid < 256) {
        float2 bb = ((const float2*)b1)[tid];
        s_bb2[tid] = pkh2(bb.x, bb.y);
        float2 vv = ((const float2*)Vw)[tid];
        float vh0 = __half2float(__float2half_rn(vv.x));
        float vh1 = __half2float(__float2half_rn(vv.y));
        s_v2h[tid] = pkh2(vh0, vh1);
        s_v2l[tid] = pkh2(vv.x - vh0, vv.y - vh1);
        float2 h0 = __ldg((const float2*)(g_hproj + (size_t)bidx0 * DIM) + tid);
        s_hp2[tid] = pkh2(h0.x, h0.y);
        float2 h1 = make_float2(0.f, 0.f);
        if (bidx0 + 1 < BS)
            h1 = __ldg((const float2*)(g_hproj + (size_t)(bidx0 + 1) * DIM) + tid);
        s_hp2[256 + tid] = pkh2(h1.x, h1.y);
    }

    // ---- A streaming-conversion indices: thread owns 2 float4 per chunk ----
    const float4* Av = (const float4*)A;     // row = 128 float4
    const int ar  = tid >> 3;                // 0..63 (and ar+64)
    const int ac4 = tid & 7;                 // float4 col within 32-col chunk

    // ---- convert ONLY chunk 0 in prologue (rest streamed in nb=0 loop) ----
    {
        float4 x0 = Av[(size_t)(m0 + ar) * 128 + ac4];
        float4 x1 = Av[(size_t)(m0 + ar + 64) * 128 + ac4];
        uint32_t h, l;
        l = cvt4_f16(x0, h);
        *(uint2*)(a_f + ar * APITCH + ac4 * 4) = make_uint2(l, h);
        l = cvt4_f16(x1, h);
        *(uint2*)(a_f + (ar + 64) * APITCH + ac4 * 4) = make_uint2(l, h);
    }
    __syncthreads();

    // ---- ldmatrix lane addresses ----
    const uint32_t a_addr0 = smbase + OFF_A +
        (uint32_t)((wm * 32 + (lane & 15)) * APITCH + (lane >> 4) * 8) * 2;
    const uint32_t a_addr1 = a_addr0 + 16 * APITCH * 2;

    const int b_n = (lane & 7) + ((lane >> 4) & 1) * 8;
    const int b_k = ((lane >> 3) & 1) * 8;
    const uint32_t bq = (uint32_t)((wn * 64 + b_n) * BPITCH + b_k) * 2;
    uint32_t b_addr[3];
    b_addr[0] = smbase + OFF_B + bq;
    b_addr[1] = b_addr[0] + BBUF;
    b_addr[2] = b_addr[1] + BBUF;

    // ---- B cp.async indices: 512 threads, 2 threads per row, 32B each ----
    const int r0 = tid >> 1;                      // 0..255
    const int jj = (tid & 1) * 2;                 // uint4 pair within row
    const uint4* gw1 = (const uint4*)g_w1f;       // row = 64 uint4
    const uint32_t bst = (uint32_t)(r0 * BPITCH + jj * 8) * 2;   // smem offset within buffer

    // ---- epilogue row info ----
    const int g = lane >> 2;
    const int t = lane & 3;
    int rowsel[2][2];
    #pragma unroll
    for (int sub = 0; sub < 2; ++sub) {
        int rl = wm * 32 + sub * 16 + g;
        rowsel[sub][0] = ((m0 + rl) / SEQ) - bidx0;
        rowsel[sub][1] = ((m0 + rl + 8) / SEQ) - bidx0;
    }

    float acc2[2][4] = {{0.f,0.f,0.f,0.f},{0.f,0.f,0.f,0.f}};

    // ---- preload B (nb=0) chunks 0,1 into bufs 0,1 (separate groups) ----
    {
        const uint4* gbase0 = gw1 + (size_t)r0 * 64 + jj;
        uint32_t s0 = smbase + OFF_B + bst;
        CPA16(s0, gbase0); CPA16(s0 + 16, gbase0 + 1);
        CPA_COMMIT();
        uint32_t s1 = smbase + OFF_B + BBUF + bst;
        CPA16(s1, gbase0 + 4); CPA16(s1 + 16, gbase0 + 5);
        CPA_COMMIT();
    }

    for (int nb = 0; nb < 2; ++nb) {
        const int n0 = nb * 256;
        const int pb = nb * 128 + wn * 32 + t;    // f16x2 pair base for this warp
        const uint4* gbase = gw1 + (size_t)(n0 + r0) * 64 + jj;

        float acc[2][8][4];
        #pragma unroll
        for (int sub = 0; sub < 2; ++sub)
            #pragma unroll
            for (int f = 0; f < 8; ++f)
                #pragma unroll
                for (int e = 0; e < 4; ++e) acc[sub][f][e] = 0.f;

        for (int kc = 0; kc < 16; ++kc) {
            const int cur = kc % 3;

            CPA_WAIT1();          // B chunk kc complete (<=1 pending: kc+1)
            __syncthreads();      // B smem + A chunk kc's STS visible to all warps

            // prefetch B chunk kc+2 into buf (kc+2)%3 (always commit for accounting)
            if (kc <= 13) {
                uint32_t dst = smbase + OFF_B + (uint32_t)((kc + 2) % 3) * BBUF + bst;
                const uint4* gp = gbase + (kc + 2) * 4;
                CPA16(dst, gp); CPA16(dst + 16, gp + 1);
            }
            CPA_COMMIT();

            // issue A-conversion loads for chunk kc+1 (nb=0 only)
            float4 ax0, ax1;
            const bool do_a = (nb == 0) && (kc < 15);
            if (do_a) {
                const size_t gofs = (size_t)(kc + 1) * 8 + ac4;
                ax0 = Av[(size_t)(m0 + ar) * 128 + gofs];
                ax1 = Av[(size_t)(m0 + ar + 64) * 128 + gofs];
            }

            #pragma unroll
            for (int ks = 0; ks < 2; ++ks) {
                const uint32_t koffA = (uint32_t)(kc * 32 + ks * 16) * 2;
                const uint32_t koffB = (uint32_t)(ks * 16) * 2;
                uint32_t a[8];
                ldsm4(a,     a_addr0 + koffA);
                ldsm4(a + 4, a_addr1 + koffA);
                #pragma unroll
                for (int half = 0; half < 2; ++half) {
                    const uint32_t hb = (uint32_t)(half * 32 * BPITCH) * 2;
                    uint32_t bf[8];
                    ldsm4(bf,     b_addr[cur] + hb + koffB);
                    ldsm4(bf + 4, b_addr[cur] + 16 * BPITCH * 2 + hb + koffB);
                    #pragma unroll
                    for (int f2 = 0; f2 < 4; ++f2) {
                        const int f = half * 4 + f2;
                        mma16816_f16(acc[0][f], a[0], a[1], a[2], a[3], bf[2*f2], bf[2*f2+1]);
                        mma16816_f16(acc[1][f], a[4], a[5], a[6], a[7], bf[2*f2], bf[2*f2+1]);
                    }
                }
            }

            // convert + store A chunk kc+1 (published by next chunk's barrier)
            if (do_a) {
                const int so = (kc + 1) * 32 + ac4 * 4;
                uint32_t h, l;
                l = cvt4_f16(ax0, h);
                *(uint2*)(a_f + ar * APITCH + so) = make_uint2(l, h);
                l = cvt4_f16(ax1, h);
                *(uint2*)(a_f + (ar + 64) * APITCH + so) = make_uint2(l, h);
            }
        }

        // ---- issue nb=1's B preload BEFORE nb=0's epilogue (overlap) ----
        if (nb == 0) {
            __syncthreads();   // all warps done reading B bufs for nb=0
            const uint4* gb1 = gw1 + (size_t)(256 + r0) * 64 + jj;
            uint32_t s0 = smbase + OFF_B + bst;
            CPA16(s0, gb1); CPA16(s0 + 16, gb1 + 1);
            CPA_COMMIT();
            uint32_t s1 = smbase + OFF_B + BBUF + bst;
            CPA16(s1, gb1 + 4); CPA16(s1 + 16, gb1 + 5);
            CPA_COMMIT();
        }

        // ---- fused epilogue: bias+relu+hp+tanh in f16x2, V-dot via tensor pipe ----
        #pragma unroll
        for (int sub = 0; sub < 2; ++sub) {
            #pragma unroll
            for (int F = 0; F < 4; ++F) {
                uint32_t tf[2][2];
                #pragma unroll
                for (int j = 0; j < 2; ++j) {
                    const int f = 2 * F + j;
                    uint32_t bb  = s_bb2[pb + f * 4];
                    uint32_t hpa = s_hp2[rowsel[sub][0] * 256 + pb + f * 4];
                    uint32_t hpb = s_hp2[rowsel[sub][1] * 256 + pb + f * 4];
                    uint32_t x0 = cvt_f16x2(acc[sub][f][1], acc[sub][f][0]);
                    uint32_t x1 = cvt_f16x2(acc[sub][f][3], acc[sub][f][2]);
                    x0 = hadd2(hmax2_0(hadd2(x0, bb)), hpa);
                    x1 = hadd2(hmax2_0(hadd2(x1, bb)), hpb);
                    tf[j][0] = htanh2(x0);
                    tf[j][1] = htanh2(x1);
                }
                uint32_t b0h = s_v2h[pb + F * 8];
                uint32_t b1h = s_v2h[pb + F * 8 + 4];
                uint32_t b0l = s_v2l[pb + F * 8];
                uint32_t b1l = s_v2l[pb + F * 8 + 4];
                mma16816_f16(acc2[sub], tf[0][0], tf[0][1], tf[1][0], tf[1][1], b0h, b1h);
                mma16816_f16(acc2[sub], tf[0][0], tf[0][1], tf[1][0], tf[1][1], b0l, b1l);
            }
        }
    }

    // ---- deterministic final score reduction (s_red aliased over B buffers) ----
    float* s_red = (float*)(sm + OFF_RED);
    __syncthreads();   // B buffers fully dead
    if (t == 0) {
        #pragma unroll
        for (int sub = 0; sub < 2; ++sub) {
            int rl = wm * 32 + sub * 16 + g;
            s_red[wn * 128 + rl]     = acc2[sub][0];   // row rl
            s_red[wn * 128 + rl + 8] = acc2[sub][2];   // row rl+8
        }
    }
    __syncthreads();
    if (tid < 128)
        g_score[m0 + tid] = ((s_red[tid] + s_red[128 + tid]) +
                             (s_red[256 + tid] + s_red[384 + tid])) + Vb[0];

    // ============ fused per-batch softmax + context (claim protocol) ============
    __threadfence();      // order score stores before counter increments
    __syncthreads();

    const int b_last = (m0 + MTILE - 1) / SEQ;
    if (tid == 0) {
        int idx = 0;
        for (int b = bidx0; b <= b_last && b < BS; ++b) {
            int cov = ((SEQ * (b + 1) - 1) >> 7) - ((SEQ * b) >> 7) + 1;
            int old = atomicAdd(&g_cnt[b], 1);
            if (old == cov - 1) s_clm[idx++] = b;
        }
    }
    __syncthreads();

    float* sw   = (float*)(sm + OFF_SW);
    float* sr2  = (float*)(sm + OFF_SR2);
    float* part = (float*)(sm + OFF_PRT);

    #pragma unroll 1
    for (int ci = 0; ci < 2; ++ci) {
        const int b = s_clm[ci];
        if (b < 0) continue;

        float sc = (tid < SEQ) ? __ldcg(&g_score[b * SEQ + tid]) : -3.4e38f;
        sr2[tid] = sc;
        __syncthreads();
        #pragma unroll
        for (int off = 256; off > 0; off >>= 1) {
            if (tid < off) sr2[tid] = fmaxf(sr2[tid], sr2[tid + off]);
            __syncthreads();
        }
        float mx = sr2[0];
        __syncthreads();

        float e = (tid < SEQ) ? __expf(sc - mx) : 0.f;
        sr2[tid] = e;
        __syncthreads();
        #pragma unroll
        for (int off = 256; off > 0; off >>= 1) {
            if (tid < off) sr2[tid] += sr2[tid + off];
            __syncthreads();
        }
        float inv = 1.f / sr2[0];

        float wt = e * inv;
        if (tid < SEQ) {
            sw[tid] = wt;
            out[(size_t)BS * DIM + (size_t)b * SEQ + tid] = wt;
        }
        __syncthreads();

        // context: 4 s-groups x 128 threads, each owns 4 consecutive e (float4)
        const int sg = tid >> 7;
        const int e4 = tid & 127;
        const float4* fb = (const float4*)(A + (size_t)b * SEQ * DIM);
        float4 acc = make_float4(0.f, 0.f, 0.f, 0.f);
        const int sBeg = sg * 90, sEnd = sBeg + 90;
        #pragma unroll 5
        for (int s = sBeg; s < sEnd; ++s) {
            float ws = sw[s];
            float4 v = fb[(size_t)s * 128 + e4];
            acc.x += ws * v.x; acc.y += ws * v.y;
            acc.z += ws * v.z; acc.w += ws * v.w;
        }
        ((float4*)(part + sg * 512))[e4] = acc;
        __syncthreads();

        float r = (part[tid] + part[512 + tid]) + (part[1024 + tid] + part[1536 + tid]);
        out[(size_t)b * DIM + tid] = r;
        __syncthreads();
    }
}

// ===================== hproj kernel: 64x64 tiles, 128 CTAs =====================
__global__ void __launch_bounds__(256) hproj_kernel(
    const float* __restrict__ A,    // hidden [1024,512]
    const float* __restrict__ B,    // W2_w   [512,512]
    const float* __restrict__ bias) // W2_b   [512]
{
    __shared__ float As[16][68];
    __shared__ float Bs[16][68];

    const int tid = threadIdx.x;
    const int tx  = tid & 15;
    const int ty  = tid >> 4;
    const int m0  = blockIdx.x * 64;
    const int n0  = blockIdx.y * 64;

    float acc[4][4];
    #pragma unroll
    for (int i = 0; i < 4; ++i)
        #pragma unroll
        for (int j = 0; j < 4; ++j) acc[i][j] = 0.f;

    const int lrow = tid >> 2, lseg = tid & 3;

    for (int kk = 0; kk < DIM; kk += 16) {
        __syncthreads();
        float4 v = *reinterpret_cast<const float4*>(A + (size_t)(m0 + lrow) * DIM + kk + lseg * 4);
        As[lseg*4+0][lrow] = v.x; As[lseg*4+1][lrow] = v.y;
        As[lseg*4+2][lrow] = v.z; As[lseg*4+3][lrow] = v.w;
        float4 w = *reinterpret_cast<const float4*>(B + (size_t)(n0 + lrow) * DIM + kk + lseg * 4);
        Bs[lseg*4+0][lrow] = w.x; Bs[lseg*4+1][lrow] = w.y;
        Bs[lseg*4+2][lrow] = w.z; Bs[lseg*4+3][lrow] = w.w;
        __syncthreads();
        #pragma unroll
        for (int k = 0; k < 16; ++k) {
            float4 a4 = *reinterpret_cast<const float4*>(&As[k][ty * 4]);
            float4 b4 = *reinterpret_cast<const float4*>(&Bs[k][tx * 4]);
            float a[4] = {a4.x, a4.y, a4.z, a4.w};
            float b[4] = {b4.x, b4.y, b4.z, b4.w};
            #pragma unroll
            for (int i = 0; i < 4; ++i)
                #pragma unroll
                for (int j = 0; j < 4; ++j)
                    acc[i][j] += a[i] * b[j];
        }
    }

    #pragma unroll
    for (int i = 0; i < 4; ++i) {
        int m = m0 + ty * 4 + i;
        #pragma unroll
        for (int j = 0; j < 4; ++j) {
            int n = n0 + tx * 4 + j;
            float v = acc[i][j] + bias[n];
            g_hproj[(size_t)m * DIM + n] = v > 0.f ? v : 0.f;
        }
    }
}

// ===================== launch =====================
extern "C" void kernel_launch(void* const* d_in, const int* in_sizes, int n_in,
                              void* d_out, int out_size)
{
    const float* hidden   = (const float*)d_in[0];
    const float* features = (const float*)d_in[1];
    const float* W1_w     = (const float*)d_in[2];
    const float* W1_b     = (const float*)d_in[3];
    const float* W2_w     = (const float*)d_in[4];
    const float* W2_b     = (const float*)d_in[5];
    const float* V_w      = (const float*)d_in[6];
    const float* V_b      = (const float*)d_in[7];
    float* out = (float*)d_out;

    cudaFuncSetAttribute(score_mma_kernel,
                         cudaFuncAttributeMaxDynamicSharedMemorySize, SMEM_BYTES);

    prep_w1_kernel<<<256, 256>>>(W1_w);
    hproj_kernel<<<dim3(16, 8), 256>>>(hidden, W2_w, W2_b);
    score_mma_kernel<<<MTOT / MTILE, 512, SMEM_BYTES>>>(features, W1_b, V_w, V_b, out);
}